// round 9
// baseline (speedup 1.0000x reference)
#include <cuda_runtime.h>
#include <math.h>

#define NMAX 100000
#define EMAX 3200000
#define FIN  512
#define HID  16
#define NCLS 40
#define CAP  128          // max neighbors per node (Poisson(32): max ~70 over 100K)

// ---- static scratch (no allocations; zero-initialized at module load) ----
__device__ int   g_cnt[NMAX];               // degree counters; ZERO at entry & exit of every call
__device__ int   g_col[NMAX * CAP];         // bucketed adjacency: node v's srcs at v*CAP
__device__ float g_dinv[NMAX];
__device__ __align__(128) float g_h [NMAX * HID];  // h = x@W1, then scaled: hs = dinv*h
__device__ __align__(128) float g_h2[NMAX * HID];  // hs2 = dinv * relu(agg1+b1)

// packed f32x2 helpers (Blackwell)
#define PACK2(d, lo, hi) \
    asm("mov.b64 %0, {%1, %2};" : "=l"(d) : "f"(lo), "f"(hi))
#define UNPACK2(lo, hi, s) \
    asm("mov.b64 {%0, %1}, %2;" : "=f"(lo), "=f"(hi) : "l"(s))
#define FMA2(d, a, b, c) \
    asm("fma.rn.f32x2 %0, %1, %2, %3;" : "=l"(d) : "l"(a), "l"(b), "l"(c))

// ---------------- bucket fill: cnt was left zero by the previous call ----------------
__global__ void k_fill(const int* __restrict__ ei, int e) {
    int i = blockIdx.x * blockDim.x + threadIdx.x;
    if (i >= e) return;
    int s = ei[i];
    int d = ei[e + i];
    int p = atomicAdd(&g_cnt[d], 1);
    if (p < CAP) g_col[(d << 7) + p] = s;
}

// ---------------- dinv + in-place scale h -> hs (4 lanes per row) ----------------
__global__ __launch_bounds__(256) void k_dinv_scale(int n) {
    int idx = blockIdx.x * 256 + threadIdx.x;
    int v = idx >> 2, fq = idx & 3;
    if (v >= n) return;
    float dv = rsqrtf((float)(g_cnt[v] + 1));   // self-loop adds 1
    if (fq == 0) g_dinv[v] = dv;
    float4* hp = (float4*)&g_h[v * HID + fq * 4];
    float4 h = *hp;
    h.x *= dv; h.y *= dv; h.z *= dv; h.w *= dv;
    *hp = h;
}

// ---------------- GEMM1: h = x @ W1 (raw, packed f32x2) ----------------
#define GROWS 256
#define GKT   32
__global__ __launch_bounds__(256) void k_gemm1(const float* __restrict__ x,
                                               const float* __restrict__ W1, int n) {
    __shared__ __align__(16) float xs[GKT][GROWS + 4];
    __shared__ __align__(16) float ws[GKT][HID];
    int t = threadIdx.x;
    int lane = t & 31, w = t >> 5;
    int rg = t >> 2, cg = t & 3;
    int r0 = blockIdx.x * GROWS;

    unsigned long long acc01[4], acc23[4];
#pragma unroll
    for (int j = 0; j < 4; j++) { acc01[j] = 0ull; acc23[j] = 0ull; }

    for (int kt = 0; kt < FIN; kt += GKT) {
        for (int idx = t; idx < GKT * HID; idx += 256) {
            int kk = idx >> 4, cc = idx & 15;
            ws[kk][cc] = W1[(kt + kk) * HID + cc];
        }
#pragma unroll 4
        for (int i = 0; i < GROWS / 8; i++) {
            int row = i * 8 + w;
            int gr = r0 + row;
            float v = 0.0f;
            if (gr < n) v = x[(long)gr * FIN + kt + lane];
            xs[lane][row] = v;
        }
        __syncthreads();
#pragma unroll
        for (int k = 0; k < GKT; k++) {
            float4 xv = *(const float4*)&xs[k][rg * 4];
            float4 wv = *(const float4*)&ws[k][cg * 4];
            unsigned long long px01, px23, pw0, pw1, pw2, pw3;
            PACK2(px01, xv.x, xv.y);
            PACK2(px23, xv.z, xv.w);
            PACK2(pw0, wv.x, wv.x);
            PACK2(pw1, wv.y, wv.y);
            PACK2(pw2, wv.z, wv.z);
            PACK2(pw3, wv.w, wv.w);
            FMA2(acc01[0], px01, pw0, acc01[0]);
            FMA2(acc23[0], px23, pw0, acc23[0]);
            FMA2(acc01[1], px01, pw1, acc01[1]);
            FMA2(acc23[1], px23, pw1, acc23[1]);
            FMA2(acc01[2], px01, pw2, acc01[2]);
            FMA2(acc23[2], px23, pw2, acc23[2]);
            FMA2(acc01[3], px01, pw3, acc01[3]);
            FMA2(acc23[3], px23, pw3, acc23[3]);
        }
        __syncthreads();
    }

    float acc[4][4];
#pragma unroll
    for (int j = 0; j < 4; j++) {
        UNPACK2(acc[0][j], acc[1][j], acc01[j]);
        UNPACK2(acc[2][j], acc[3][j], acc23[j]);
    }
#pragma unroll
    for (int i = 0; i < 4; i++) {
        int gr = r0 + rg * 4 + i;
        if (gr < n) {
            float4 o = make_float4(acc[i][0], acc[i][1], acc[i][2], acc[i][3]);
            *(float4*)&g_h[gr * HID + cg * 4] = o;
        }
    }
}

// ---------------- gather 1: hs2 = dv * relu(dv*(Σ hs[nbr] + hs[self]) + b1) ----------------
// lane layout: slot = lane>>2 (8 neighbor slots), fq = lane&3 (4 float4 feature lanes)
__global__ __launch_bounds__(256) void k_gather1(const float* __restrict__ b1, int n) {
    int v = blockIdx.x * 8 + (threadIdx.x >> 5);
    if (v >= n) return;
    int lane = threadIdx.x & 31;
    int slot = lane >> 2, fq = lane & 3;

    int beg = v << 7;
    int dg  = g_cnt[v];

    float4 acc = make_float4(0.f, 0.f, 0.f, 0.f);
    int j = slot;
    for (; j + 8 < dg; j += 16) {
        int s0 = __ldg(&g_col[beg + j]);
        int s1 = __ldg(&g_col[beg + j + 8]);
        float4 h0 = *(const float4*)&g_h[s0 * HID + fq * 4];
        float4 h1 = *(const float4*)&g_h[s1 * HID + fq * 4];
        acc.x += h0.x + h1.x; acc.y += h0.y + h1.y;
        acc.z += h0.z + h1.z; acc.w += h0.w + h1.w;
    }
    if (j < dg) {
        int s = __ldg(&g_col[beg + j]);
        float4 h0 = *(const float4*)&g_h[s * HID + fq * 4];
        acc.x += h0.x; acc.y += h0.y; acc.z += h0.z; acc.w += h0.w;
    }
#pragma unroll
    for (int off = 4; off <= 16; off <<= 1) {
        acc.x += __shfl_xor_sync(0xffffffffu, acc.x, off);
        acc.y += __shfl_xor_sync(0xffffffffu, acc.y, off);
        acc.z += __shfl_xor_sync(0xffffffffu, acc.z, off);
        acc.w += __shfl_xor_sync(0xffffffffu, acc.w, off);
    }

    float dv = g_dinv[v];
    float4 self = *(const float4*)&g_h[v * HID + fq * 4];   // already dinv-scaled
    float4 bb   = *(const float4*)&b1[fq * 4];
    float4 o;
    o.x = dv * fmaxf(dv * (acc.x + self.x) + bb.x, 0.0f);
    o.y = dv * fmaxf(dv * (acc.y + self.y) + bb.y, 0.0f);
    o.z = dv * fmaxf(dv * (acc.z + self.z) + bb.z, 0.0f);
    o.w = dv * fmaxf(dv * (acc.w + self.w) + bb.w, 0.0f);
    if (lane < 4) *(float4*)&g_h2[v * HID + fq * 4] = o;
}

// ---------------- gather 2 + W2 + log_softmax; resets g_cnt to 0 ----------------
__global__ __launch_bounds__(256) void k_gather2_final(const float* __restrict__ W2,
                                                       const float* __restrict__ b2,
                                                       float* __restrict__ out, int n) {
    __shared__ float w2s[HID * NCLS];
    __shared__ float b2s[NCLS];
    int t = threadIdx.x;
    for (int idx = t; idx < HID * NCLS; idx += 256) w2s[idx] = W2[idx];
    if (t < NCLS) b2s[t] = b2[t];
    __syncthreads();

    int v = blockIdx.x * 8 + (t >> 5);
    if (v >= n) return;
    int lane = t & 31;
    int slot = lane >> 2, fq = lane & 3;

    int beg = v << 7;
    int dg  = g_cnt[v];
    if (lane == 0) g_cnt[v] = 0;   // restore invariant: cnt==0 at call exit

    float4 acc = make_float4(0.f, 0.f, 0.f, 0.f);
    int j = slot;
    for (; j + 8 < dg; j += 16) {
        int s0 = __ldg(&g_col[beg + j]);
        int s1 = __ldg(&g_col[beg + j + 8]);
        float4 h0 = *(const float4*)&g_h2[s0 * HID + fq * 4];
        float4 h1 = *(const float4*)&g_h2[s1 * HID + fq * 4];
        acc.x += h0.x + h1.x; acc.y += h0.y + h1.y;
        acc.z += h0.z + h1.z; acc.w += h0.w + h1.w;
    }
    if (j < dg) {
        int s = __ldg(&g_col[beg + j]);
        float4 h0 = *(const float4*)&g_h2[s * HID + fq * 4];
        acc.x += h0.x; acc.y += h0.y; acc.z += h0.z; acc.w += h0.w;
    }
#pragma unroll
    for (int off = 4; off <= 16; off <<= 1) {
        acc.x += __shfl_xor_sync(0xffffffffu, acc.x, off);
        acc.y += __shfl_xor_sync(0xffffffffu, acc.y, off);
        acc.z += __shfl_xor_sync(0xffffffffu, acc.z, off);
        acc.w += __shfl_xor_sync(0xffffffffu, acc.w, off);
    }

    float dv = g_dinv[v];
    float4 self = *(const float4*)&g_h2[v * HID + fq * 4];
    float av[4];
    av[0] = dv * (acc.x + self.x);
    av[1] = dv * (acc.y + self.y);
    av[2] = dv * (acc.z + self.z);
    av[3] = dv * (acc.w + self.w);

    float a[HID];
#pragma unroll
    for (int k = 0; k < HID; k++)
        a[k] = __shfl_sync(0xffffffffu, av[k & 3], k >> 2);

    float v1 = b2s[lane];
#pragma unroll
    for (int k = 0; k < HID; k++) v1 += a[k] * w2s[k * NCLS + lane];

    float v2 = __int_as_float(0xff800000);  // -inf
    if (lane < 8) {
        int c2 = 32 + lane;
        v2 = b2s[c2];
#pragma unroll
        for (int k = 0; k < HID; k++) v2 += a[k] * w2s[k * NCLS + c2];
    }

    float m = fmaxf(v1, v2);
#pragma unroll
    for (int off = 16; off >= 1; off >>= 1)
        m = fmaxf(m, __shfl_xor_sync(0xffffffffu, m, off));

    float se = __expf(v1 - m) + ((lane < 8) ? __expf(v2 - m) : 0.0f);
#pragma unroll
    for (int off = 16; off >= 1; off >>= 1)
        se += __shfl_xor_sync(0xffffffffu, se, off);

    float lse = __logf(se);
    out[v * NCLS + lane] = v1 - m - lse;
    if (lane < 8) out[v * NCLS + 32 + lane] = v2 - m - lse;
}

extern "C" void kernel_launch(void* const* d_in, const int* in_sizes, int n_in,
                              void* d_out, int out_size) {
    const float* x  = (const float*)d_in[0];
    const float* W1 = (const float*)d_in[1];
    const float* b1 = (const float*)d_in[2];
    const float* W2 = (const float*)d_in[3];
    const float* b2 = (const float*)d_in[4];
    const int*   ei = (const int*)d_in[5];   // int32: JAX x64 disabled

    int n = in_sizes[0] / FIN;
    int e = in_sizes[5] / 2;
    if (n > NMAX) n = NMAX;
    if (e > EMAX) e = EMAX;

    int eb  = (e + 255) / 256;
    int gnb = (n + 7) / 8;                 // warp-per-node grids
    int snb = (n * 4 + 255) / 256;         // 4 lanes per row
    int ggb = (n + GROWS - 1) / GROWS;

    // One-time host-side stream/event setup (first call is outside capture).
    static cudaStream_t s2 = nullptr;
    static cudaEvent_t  evF = nullptr, evJ = nullptr;
    static int          tried = 0;
    if (!tried) {
        tried = 1;
        if (cudaStreamCreateWithFlags(&s2, cudaStreamNonBlocking) != cudaSuccess) s2 = nullptr;
        if (s2) {
            if (cudaEventCreateWithFlags(&evF, cudaEventDisableTiming) != cudaSuccess ||
                cudaEventCreateWithFlags(&evJ, cudaEventDisableTiming) != cudaSuccess) {
                s2 = nullptr;
            }
        }
    }

    if (s2) {
        // Fork: gemm1 on s2 overlaps bucket fill on stream 0.
        cudaEventRecord(evF, 0);
        cudaStreamWaitEvent(s2, evF, 0);
        k_gemm1<<<ggb, 256, 0, s2>>>(x, W1, n);
        cudaEventRecord(evJ, s2);

        k_fill<<<eb, 256>>>(ei, e);

        cudaStreamWaitEvent(0, evJ, 0);    // join: need h AND cnt
    } else {
        k_gemm1<<<ggb, 256>>>(x, W1, n);
        k_fill<<<eb, 256>>>(ei, e);
    }

    k_dinv_scale<<<snb, 256>>>(n);
    k_gather1<<<gnb, 256>>>(b1, n);
    k_gather2_final<<<gnb, 256>>>(W2, b2, (float*)d_out, n);
}

// round 10
// speedup vs baseline: 1.1943x; 1.1943x over previous
#include <cuda_runtime.h>
#include <math.h>

#define NMAX 100000
#define EMAX 3200000
#define FIN  512
#define HID  16
#define NCLS 40
#define CAP  128          // max neighbors per node (Poisson(32): P(deg>=128) ~ e^-60)

// ---- static scratch (no allocations; zero-initialized at module load) ----
__device__ int   g_cnt[NMAX];               // degree counters; ZERO at entry & exit of every call
__device__ int   g_col[NMAX * CAP];         // bucketed adjacency: node v's srcs at v*CAP
__device__ float g_dinv[NMAX];
__device__ __align__(128) float g_h [NMAX * HID];  // h = x@W1, then scaled in-place: hs = dinv*h
__device__ __align__(128) float g_h2[NMAX * HID];  // hs2 = dinv * relu(agg1+b1)

// packed f32x2 helpers (Blackwell)
#define PACK2(d, lo, hi) \
    asm("mov.b64 %0, {%1, %2};" : "=l"(d) : "f"(lo), "f"(hi))
#define UNPACK2(lo, hi, s) \
    asm("mov.b64 {%0, %1}, %2;" : "=f"(lo), "=f"(hi) : "l"(s))
#define FMA2(d, a, b, c) \
    asm("fma.rn.f32x2 %0, %1, %2, %3;" : "=l"(d) : "l"(a), "l"(b), "l"(c))

// ---------------- bucket fill: cnt was left zero by the previous call ----------------
__global__ void k_fill(const int* __restrict__ ei, int e) {
    int i = blockIdx.x * blockDim.x + threadIdx.x;
    if (i >= e) return;
    int s = ei[i];
    int d = ei[e + i];
    int p = atomicAdd(&g_cnt[d], 1);
    if (p < CAP) g_col[(d << 7) + p] = s;
}

// ---------------- dinv + in-place scale h -> hs (4 lanes per row) ----------------
__global__ __launch_bounds__(256) void k_dinv_scale(int n) {
    int idx = blockIdx.x * 256 + threadIdx.x;
    int v = idx >> 2, fq = idx & 3;
    if (v >= n) return;
    float dv = rsqrtf((float)(g_cnt[v] + 1));   // self-loop adds 1
    if (fq == 0) g_dinv[v] = dv;
    float4* hp = (float4*)&g_h[v * HID + fq * 4];
    float4 h = *hp;
    h.x *= dv; h.y *= dv; h.z *= dv; h.w *= dv;
    *hp = h;
}

// ---------------- GEMM1: h = x @ W1 (raw); bank-conflict-free smem ----------------
#define GROWS 256
#define GKT   32
#define XPAD  (GKT + 1)   // stride 33 floats: conflict-free scalar access both ways
__global__ __launch_bounds__(256) void k_gemm1(const float* __restrict__ x,
                                               const float* __restrict__ W1, int n) {
    __shared__ float xs[GROWS][XPAD];                       // 33.8 KB, row-major
    __shared__ __align__(16) unsigned long long wsd[GKT][HID];  // (w,w) packed, 4 KB
    int t = threadIdx.x;
    int rg = t >> 2, cg = t & 3;          // 64 row-groups x 4 col-groups
    int c  = t & 7,  rb = t >> 3;         // loader: k-chunk 0..7, row-base 0..31
    int r0 = blockIdx.x * GROWS;

    unsigned long long acc01[4], acc23[4];
#pragma unroll
    for (int j = 0; j < 4; j++) { acc01[j] = 0ull; acc23[j] = 0ull; }

    for (int kt = 0; kt < FIN; kt += GKT) {
        // W tile: duplicate each float into both halves of a u64
        for (int idx = t; idx < GKT * HID; idx += 256) {
            int kk = idx >> 4, cc = idx & 15;
            float wv = W1[(kt + kk) * HID + cc];
            unsigned long long p; PACK2(p, wv, wv);
            wsd[kk][cc] = p;
        }
        // x tile: row-major, scalar stores (banks (row + 4c + j) % 32 -> conflict-free)
#pragma unroll
        for (int i = 0; i < GROWS / 32; i++) {
            int row = rb + i * 32;
            int gr = r0 + row;
            float4 v = make_float4(0.f, 0.f, 0.f, 0.f);
            if (gr < n) v = *(const float4*)&x[(long)gr * FIN + kt + c * 4];
            xs[row][c * 4 + 0] = v.x;
            xs[row][c * 4 + 1] = v.y;
            xs[row][c * 4 + 2] = v.z;
            xs[row][c * 4 + 3] = v.w;
        }
        __syncthreads();
#pragma unroll
        for (int k = 0; k < GKT; k++) {
            // scalar LDS: banks (4rg + i + k) % 32 -> conflict-free
            float a0 = xs[rg * 4 + 0][k];
            float a1 = xs[rg * 4 + 1][k];
            float a2 = xs[rg * 4 + 2][k];
            float a3 = xs[rg * 4 + 3][k];
            unsigned long long px01, px23;
            PACK2(px01, a0, a1);
            PACK2(px23, a2, a3);
            unsigned long long pw0 = wsd[k][cg * 4 + 0];
            unsigned long long pw1 = wsd[k][cg * 4 + 1];
            unsigned long long pw2 = wsd[k][cg * 4 + 2];
            unsigned long long pw3 = wsd[k][cg * 4 + 3];
            FMA2(acc01[0], px01, pw0, acc01[0]);
            FMA2(acc23[0], px23, pw0, acc23[0]);
            FMA2(acc01[1], px01, pw1, acc01[1]);
            FMA2(acc23[1], px23, pw1, acc23[1]);
            FMA2(acc01[2], px01, pw2, acc01[2]);
            FMA2(acc23[2], px23, pw2, acc23[2]);
            FMA2(acc01[3], px01, pw3, acc01[3]);
            FMA2(acc23[3], px23, pw3, acc23[3]);
        }
        __syncthreads();
    }

    float acc[4][4];
#pragma unroll
    for (int j = 0; j < 4; j++) {
        UNPACK2(acc[0][j], acc[1][j], acc01[j]);
        UNPACK2(acc[2][j], acc[3][j], acc23[j]);
    }
#pragma unroll
    for (int i = 0; i < 4; i++) {
        int gr = r0 + rg * 4 + i;
        if (gr < n) {
            float4 o = make_float4(acc[i][0], acc[i][1], acc[i][2], acc[i][3]);
            *(float4*)&g_h[gr * HID + cg * 4] = o;
        }
    }
}

// ---------------- gather 1: hs2 = dv * relu(dv*(Σ hs[nbr] + hs[self]) + b1) ----------------
// lane layout: slot = lane>>2 (8 slots), fq = lane&3 (4 float4 feature lanes); unroll x4
__global__ __launch_bounds__(256) void k_gather1(const float* __restrict__ b1, int n) {
    int v = blockIdx.x * 8 + (threadIdx.x >> 5);
    if (v >= n) return;
    int lane = threadIdx.x & 31;
    int slot = lane >> 2, fq = lane & 3;

    int beg = v << 7;
    int dg  = g_cnt[v];

    float4 acc = make_float4(0.f, 0.f, 0.f, 0.f);
    int j = slot;
    for (; j + 24 < dg; j += 32) {
        int s0 = __ldg(&g_col[beg + j]);
        int s1 = __ldg(&g_col[beg + j + 8]);
        int s2 = __ldg(&g_col[beg + j + 16]);
        int s3 = __ldg(&g_col[beg + j + 24]);
        float4 h0 = *(const float4*)&g_h[s0 * HID + fq * 4];
        float4 h1 = *(const float4*)&g_h[s1 * HID + fq * 4];
        float4 h2 = *(const float4*)&g_h[s2 * HID + fq * 4];
        float4 h3 = *(const float4*)&g_h[s3 * HID + fq * 4];
        acc.x += (h0.x + h1.x) + (h2.x + h3.x);
        acc.y += (h0.y + h1.y) + (h2.y + h3.y);
        acc.z += (h0.z + h1.z) + (h2.z + h3.z);
        acc.w += (h0.w + h1.w) + (h2.w + h3.w);
    }
#pragma unroll
    for (int u = 0; u < 3; u++) {
        int jj = j + u * 8;
        if (jj < dg) {
            int s = __ldg(&g_col[beg + jj]);
            float4 h = *(const float4*)&g_h[s * HID + fq * 4];
            acc.x += h.x; acc.y += h.y; acc.z += h.z; acc.w += h.w;
        }
    }
#pragma unroll
    for (int off = 4; off <= 16; off <<= 1) {
        acc.x += __shfl_xor_sync(0xffffffffu, acc.x, off);
        acc.y += __shfl_xor_sync(0xffffffffu, acc.y, off);
        acc.z += __shfl_xor_sync(0xffffffffu, acc.z, off);
        acc.w += __shfl_xor_sync(0xffffffffu, acc.w, off);
    }

    float dv = g_dinv[v];
    float4 self = *(const float4*)&g_h[v * HID + fq * 4];   // already dinv-scaled
    float4 bb   = *(const float4*)&b1[fq * 4];
    float4 o;
    o.x = dv * fmaxf(dv * (acc.x + self.x) + bb.x, 0.0f);
    o.y = dv * fmaxf(dv * (acc.y + self.y) + bb.y, 0.0f);
    o.z = dv * fmaxf(dv * (acc.z + self.z) + bb.z, 0.0f);
    o.w = dv * fmaxf(dv * (acc.w + self.w) + bb.w, 0.0f);
    if (lane < 4) *(float4*)&g_h2[v * HID + fq * 4] = o;
}

// ---------------- gather 2 + W2 + log_softmax; resets g_cnt to 0 ----------------
__global__ __launch_bounds__(256) void k_gather2_final(const float* __restrict__ W2,
                                                       const float* __restrict__ b2,
                                                       float* __restrict__ out, int n) {
    __shared__ float w2s[HID * NCLS];
    __shared__ float b2s[NCLS];
    int t = threadIdx.x;
    for (int idx = t; idx < HID * NCLS; idx += 256) w2s[idx] = W2[idx];
    if (t < NCLS) b2s[t] = b2[t];
    __syncthreads();

    int v = blockIdx.x * 8 + (t >> 5);
    if (v >= n) return;
    int lane = t & 31;
    int slot = lane >> 2, fq = lane & 3;

    int beg = v << 7;
    int dg  = g_cnt[v];
    if (lane == 0) g_cnt[v] = 0;   // restore invariant: cnt==0 at call exit

    float4 acc = make_float4(0.f, 0.f, 0.f, 0.f);
    int j = slot;
    for (; j + 24 < dg; j += 32) {
        int s0 = __ldg(&g_col[beg + j]);
        int s1 = __ldg(&g_col[beg + j + 8]);
        int s2 = __ldg(&g_col[beg + j + 16]);
        int s3 = __ldg(&g_col[beg + j + 24]);
        float4 h0 = *(const float4*)&g_h2[s0 * HID + fq * 4];
        float4 h1 = *(const float4*)&g_h2[s1 * HID + fq * 4];
        float4 h2 = *(const float4*)&g_h2[s2 * HID + fq * 4];
        float4 h3 = *(const float4*)&g_h2[s3 * HID + fq * 4];
        acc.x += (h0.x + h1.x) + (h2.x + h3.x);
        acc.y += (h0.y + h1.y) + (h2.y + h3.y);
        acc.z += (h0.z + h1.z) + (h2.z + h3.z);
        acc.w += (h0.w + h1.w) + (h2.w + h3.w);
    }
#pragma unroll
    for (int u = 0; u < 3; u++) {
        int jj = j + u * 8;
        if (jj < dg) {
            int s = __ldg(&g_col[beg + jj]);
            float4 h = *(const float4*)&g_h2[s * HID + fq * 4];
            acc.x += h.x; acc.y += h.y; acc.z += h.z; acc.w += h.w;
        }
    }
#pragma unroll
    for (int off = 4; off <= 16; off <<= 1) {
        acc.x += __shfl_xor_sync(0xffffffffu, acc.x, off);
        acc.y += __shfl_xor_sync(0xffffffffu, acc.y, off);
        acc.z += __shfl_xor_sync(0xffffffffu, acc.z, off);
        acc.w += __shfl_xor_sync(0xffffffffu, acc.w, off);
    }

    float dv = g_dinv[v];
    float4 self = *(const float4*)&g_h2[v * HID + fq * 4];
    float av[4];
    av[0] = dv * (acc.x + self.x);
    av[1] = dv * (acc.y + self.y);
    av[2] = dv * (acc.z + self.z);
    av[3] = dv * (acc.w + self.w);

    float a[HID];
#pragma unroll
    for (int k = 0; k < HID; k++)
        a[k] = __shfl_sync(0xffffffffu, av[k & 3], k >> 2);

    float v1 = b2s[lane];
#pragma unroll
    for (int k = 0; k < HID; k++) v1 += a[k] * w2s[k * NCLS + lane];

    float v2 = __int_as_float(0xff800000);  // -inf
    if (lane < 8) {
        int c2 = 32 + lane;
        v2 = b2s[c2];
#pragma unroll
        for (int k = 0; k < HID; k++) v2 += a[k] * w2s[k * NCLS + c2];
    }

    float m = fmaxf(v1, v2);
#pragma unroll
    for (int off = 16; off >= 1; off >>= 1)
        m = fmaxf(m, __shfl_xor_sync(0xffffffffu, m, off));

    float se = __expf(v1 - m) + ((lane < 8) ? __expf(v2 - m) : 0.0f);
#pragma unroll
    for (int off = 16; off >= 1; off >>= 1)
        se += __shfl_xor_sync(0xffffffffu, se, off);

    float lse = __logf(se);
    out[v * NCLS + lane] = v1 - m - lse;
    if (lane < 8) out[v * NCLS + 32 + lane] = v2 - m - lse;
}

extern "C" void kernel_launch(void* const* d_in, const int* in_sizes, int n_in,
                              void* d_out, int out_size) {
    const float* x  = (const float*)d_in[0];
    const float* W1 = (const float*)d_in[1];
    const float* b1 = (const float*)d_in[2];
    const float* W2 = (const float*)d_in[3];
    const float* b2 = (const float*)d_in[4];
    const int*   ei = (const int*)d_in[5];   // int32: JAX x64 disabled

    int n = in_sizes[0] / FIN;
    int e = in_sizes[5] / 2;
    if (n > NMAX) n = NMAX;
    if (e > EMAX) e = EMAX;

    int eb  = (e + 255) / 256;
    int gnb = (n + 7) / 8;                 // warp-per-node grids
    int snb = (n * 4 + 255) / 256;         // 4 lanes per row
    int ggb = (n + GROWS - 1) / GROWS;

    // One-time host-side stream/event setup (first call is outside capture).
    static cudaStream_t s2 = nullptr;
    static cudaEvent_t  evF = nullptr, evJ = nullptr;
    static int          tried = 0;
    if (!tried) {
        tried = 1;
        if (cudaStreamCreateWithFlags(&s2, cudaStreamNonBlocking) != cudaSuccess) s2 = nullptr;
        if (s2) {
            if (cudaEventCreateWithFlags(&evF, cudaEventDisableTiming) != cudaSuccess ||
                cudaEventCreateWithFlags(&evJ, cudaEventDisableTiming) != cudaSuccess) {
                s2 = nullptr;
            }
        }
    }

    if (s2) {
        // Fork: gemm1 on s2 overlaps bucket fill on stream 0.
        cudaEventRecord(evF, 0);
        cudaStreamWaitEvent(s2, evF, 0);
        k_gemm1<<<ggb, 256, 0, s2>>>(x, W1, n);
        cudaEventRecord(evJ, s2);

        k_fill<<<eb, 256>>>(ei, e);

        cudaStreamWaitEvent(0, evJ, 0);    // join: need h AND cnt
    } else {
        k_gemm1<<<ggb, 256>>>(x, W1, n);
        k_fill<<<eb, 256>>>(ei, e);
    }

    k_dinv_scale<<<snb, 256>>>(n);
    k_gather1<<<gnb, 256>>>(b1, n);
    k_gather2_final<<<gnb, 256>>>(W2, b2, (float*)d_out, n);
}